// round 6
// baseline (speedup 1.0000x reference)
#include <cuda_runtime.h>

// Problem constants (fixed shapes for SNNModel_67611375174158)
#define B_DIM   128
#define T_DIM   128
#define BT      (B_DIM * T_DIM)          // 16384 rows
#define NIN     2312                     // 2*34*34
#define NCH     (NIN / 4)                // 578 int4 chunks per row
#define NFULL   (NCH / 32)               // 18 full 32-chunk groups
#define NTAIL   (NCH - NFULL * 32)       // 2 tail chunks
#define NHID    2048
#define NOUT    10
#define ALPHA_F 0.001f

#define NS_OUT  (BT * NOUT)                       // 163840 spike floats
#define TOT_OUT (NS_OUT + NHID * 16 + NOUT * 16)  // 196768 total floats

#define NROWBLK (BT / 8)                          // 2048 row blocks (8 warps each)
#define NBLK    (NROWBLK + 1)                     // +1 table block

// Scratch (no allocations allowed -> __device__ globals)
__device__ unsigned char      g_accT[BT];     // [t*128+b]: acc&15 | any<<4
__device__ unsigned char      g_accB[BT];     // [b*128+t]: acc&15 | any<<4
__device__ unsigned long long g_A1pack;       // 16 x 4-bit A1 table
__device__ unsigned           g_spk[16];      // spike bitmask per s (10 bits over k)
__device__ int                g_c0[16], g_c1[16];
__device__ unsigned           g_S1[BT / 4];   // packed s1 bytes, b-major [b*32+w]
__device__ int                g_count;        // last-block-done counter (reset by tail)

// ---------------------------------------------------------------------------
// Kernel 1: frame scan (2048 blocks, one warp per (b,t) row) + table block
// + last-block tail that performs the sequential scan and publishes results.
// ---------------------------------------------------------------------------
__global__ void __launch_bounds__(256) k_main(const int*   __restrict__ frames,
                                              const int*   __restrict__ ids,
                                              const int*   __restrict__ nid0,
                                              const float* __restrict__ vth0,
                                              const float* __restrict__ map0,
                                              const float* __restrict__ map1,
                                              const float* __restrict__ vth1) {
    __shared__ int4 sIds[NCH];
    __shared__ int  sA1[16];
    __shared__ int  sLast;
    __shared__ unsigned      sM[4];
    __shared__ unsigned char sDt8[T_DIM];
    __shared__ unsigned char sAm8[T_DIM];
    __shared__ int  sc0[16], sc1[16];

    int tid  = threadIdx.x;
    int lane = tid & 31;

    if (blockIdx.x == NROWBLK) {
        // ---- Table block: A1 pack + spike LUT (runs under the DRAM stream) ----
        if (tid < 16) sA1[tid] = 0;
        __syncthreads();
        int loc[16];
        #pragma unroll
        for (int p = 0; p < 16; p++) loc[p] = 0;
        for (int j = tid; j < NHID; j += 256) {
            int   nid = __ldg(&nid0[j]);
            float vt  = __ldg(&vth0[j]);
            const float4* r = reinterpret_cast<const float4*>(map0 + (size_t)j * 16);
            #pragma unroll
            for (int q = 0; q < 4; q++) {
                float4 mv = __ldg(&r[q]);
                if (mv.x >= vt) loc[q * 4 + 0] ^= nid;
                if (mv.y >= vt) loc[q * 4 + 1] ^= nid;
                if (mv.z >= vt) loc[q * 4 + 2] ^= nid;
                if (mv.w >= vt) loc[q * 4 + 3] ^= nid;
            }
        }
        #pragma unroll
        for (int p = 0; p < 16; p++)
            if (loc[p]) atomicXor(&sA1[p], loc[p]);
        __syncthreads();
        if (tid == 0) {
            unsigned long long pk = 0;
            #pragma unroll
            for (int p = 0; p < 16; p++)
                pk |= (unsigned long long)(sA1[p] & 15) << (4 * p);
            g_A1pack = pk;
        }
        if (tid < 160) {
            int k = tid >> 4, s = tid & 15;
            unsigned bit = (__ldg(&map1[k * 16 + s]) >= __ldg(&vth1[k])) ? (1u << k) : 0u;
            // reduce 10 k-bits per s via shfl within warp halves (s in lane%16)
            #pragma unroll
            for (int o = 16; o >= 16; o >>= 1) {} // no-op keep structure
            atomicOr(&g_spk[s], bit | 0x80000000u); // bit31 marker avoids stale-zero concern
        }
        // NOTE: g_spk accumulates across replays via atomicOr; make it exact:
        // overwrite cleanly below after a sync using plain stores.
        __syncthreads();
        if (tid < 16) {
            unsigned m = 0;
            #pragma unroll
            for (int k = 0; k < NOUT; k++)
                if (__ldg(&map1[k * 16 + tid]) >= __ldg(&vth1[k])) m |= 1u << k;
            g_spk[tid] = m;   // plain store: deterministic, replay-safe
        }
    } else {
        // ---- Row blocks: stage ids, scan 8 rows ----
        const int4* ids4 = reinterpret_cast<const int4*>(ids);
        for (int i = tid; i < NCH; i += 256) sIds[i] = ids4[i];
        __syncthreads();

        int wid = (blockIdx.x * 256 + tid) >> 5;   // row = b*T + t
        const int4* row4 = reinterpret_cast<const int4*>(frames + (size_t)wid * NIN);

        unsigned x = 0, any = 0;
        #pragma unroll 6
        for (int g = 0; g < NFULL; g++) {
            int4 v  = __ldg(&row4[g * 32 + lane]);
            int4 id = sIds[g * 32 + lane];
            if (v.x) x ^= (unsigned)id.x & 15u;
            if (v.y) x ^= (unsigned)id.y & 15u;
            if (v.z) x ^= (unsigned)id.z & 15u;
            if (v.w) x ^= (unsigned)id.w & 15u;
            any |= (unsigned)(v.x | v.y | v.z | v.w);
        }
        if (lane < NTAIL) {
            int4 v  = __ldg(&row4[NFULL * 32 + lane]);
            int4 id = sIds[NFULL * 32 + lane];
            if (v.x) x ^= (unsigned)id.x & 15u;
            if (v.y) x ^= (unsigned)id.y & 15u;
            if (v.z) x ^= (unsigned)id.z & 15u;
            if (v.w) x ^= (unsigned)id.w & 15u;
            any |= (unsigned)(v.x | v.y | v.z | v.w);
        }

        unsigned acc  = __reduce_xor_sync(0xFFFFFFFFu, x);
        unsigned anyv = __reduce_or_sync(0xFFFFFFFFu, any);
        if (lane == 0) {
            int b = wid >> 7, t = wid & 127;
            unsigned char v = (unsigned char)((acc & 15u) | (anyv ? 16u : 0u));
            g_accT[t * 128 + b] = v;
            g_accB[b * 128 + t] = v;
        }
    }

    // ---- Last-block-done gate ----
    __syncthreads();
    __threadfence();
    if (tid == 0) {
        int v = atomicAdd(&g_count, 1);
        sLast = (v == NBLK - 1);
    }
    __syncthreads();
    if (!sLast) return;
    __threadfence();   // acquire: make all blocks' writes visible

    // ================= TAIL (one block, hot clocks, data in L2) =============

    // Phase B: has[t] from t-major acc, ballot into 128-bit mask
    if (tid < 128) {
        const unsigned* w = reinterpret_cast<const unsigned*>(g_accT) + tid * 32;
        unsigned o = 0;
        #pragma unroll
        for (int k = 0; k < 32; k++) o |= __ldg(&w[k]);
        int has = (o & 0x10101010u) ? 1 : 0;
        unsigned bal = __ballot_sync(0xFFFFFFFFu, has);
        if (lane == 0) sM[tid >> 5] = bal;
    }
    if (tid >= 128 && tid < 144) { sc0[tid - 128] = 0; sc1[tid - 128] = 0; }
    __syncthreads();

    // Phase C: per-t delta_t from previous active timestep (clz-based)
    if (tid < 128) {
        int t = tid;
        int word = t >> 5, bit = t & 31;
        int active = (sM[word] >> bit) & 1;
        unsigned m = bit ? (sM[word] & ((1u << bit) - 1u)) : 0u;
        int tl = 0;
        int w = word;
        while (true) {
            if (m) { tl = (w << 5) + 31 - __clz(m); break; }
            if (--w < 0) break;
            m = sM[w];
        }
        sDt8[t] = (unsigned char)(active ? ((t - tl) & 15) : 0);
        sAm8[t] = (unsigned char)(active ? 0x0F : 0x00);
    }
    __syncthreads();

    // Phase D: register-resident per-batch scan (thread b < 128)
    if (tid < 128) {
        int b = tid;
        unsigned aw[32];
        {
            const uint4* rb = reinterpret_cast<const uint4*>(g_accB) + b * 8;
            #pragma unroll
            for (int r = 0; r < 8; r++) {
                uint4 v = __ldg(&rb[r]);
                aw[r * 4 + 0] = v.x; aw[r * 4 + 1] = v.y;
                aw[r * 4 + 2] = v.z; aw[r * 4 + 3] = v.w;
            }
        }
        unsigned long long A1p = g_A1pack;
        const unsigned* dtW = reinterpret_cast<const unsigned*>(sDt8);
        const unsigned* amW = reinterpret_cast<const unsigned*>(sAm8);

        unsigned s0 = 0, s1 = 0;
        unsigned long long h0lo = 0, h0hi = 0, h1lo = 0, h1hi = 0;

        #pragma unroll 4
        for (int w = 0; w < 32; w++) {
            unsigned am = amW[w];
            unsigned dt = dtW[w];
            unsigned x  = (aw[w] & am) ^ dt;
            unsigned pk = 0;
            #pragma unroll
            for (int j = 0; j < 4; j++) {
                unsigned amb = (am >> (8 * j));
                unsigned xb  = (x  >> (8 * j)) & 15u;
                s0 ^= xb;
                unsigned long long act64 = (unsigned long long)(amb & 1u);
                unsigned long long inc0  = act64 << ((s0 & 7u) << 3);
                h0lo += (s0 < 8u) ? inc0 : 0ULL;
                h0hi += (s0 < 8u) ? 0ULL : inc0;
                unsigned a1 = (unsigned)(A1p >> (s0 << 2)) & amb & 15u;
                unsigned db = (dt >> (8 * j)) & 15u;
                s1 ^= db ^ a1;
                unsigned long long inc1 = act64 << ((s1 & 7u) << 3);
                h1lo += (s1 < 8u) ? inc1 : 0ULL;
                h1hi += (s1 < 8u) ? 0ULL : inc1;
                unsigned sb = s1 | (((amb & 1u) - 1u) & 0xFFu);  // 0xFF if inactive
                pk |= sb << (8 * j);
            }
            g_S1[b * 32 + w] = pk;
        }

        // Histogram finalize: expand byte bins to 16-bit lanes, warp-reduce.
        const unsigned long long EM = 0x00FF00FF00FF00FFULL;
        unsigned long long e0 = h0lo & EM, e1 = (h0lo >> 8) & EM;
        unsigned long long e2 = h0hi & EM, e3 = (h0hi >> 8) & EM;
        unsigned long long f0 = h1lo & EM, f1 = (h1lo >> 8) & EM;
        unsigned long long f2 = h1hi & EM, f3 = (h1hi >> 8) & EM;
        #pragma unroll
        for (int o = 16; o; o >>= 1) {
            e0 += __shfl_xor_sync(0xFFFFFFFFu, e0, o);
            e1 += __shfl_xor_sync(0xFFFFFFFFu, e1, o);
            e2 += __shfl_xor_sync(0xFFFFFFFFu, e2, o);
            e3 += __shfl_xor_sync(0xFFFFFFFFu, e3, o);
            f0 += __shfl_xor_sync(0xFFFFFFFFu, f0, o);
            f1 += __shfl_xor_sync(0xFFFFFFFFu, f1, o);
            f2 += __shfl_xor_sync(0xFFFFFFFFu, f2, o);
            f3 += __shfl_xor_sync(0xFFFFFFFFu, f3, o);
        }
        if (lane < 16) {
            int slot = (lane & 7) >> 1;
            unsigned long long c0 = (lane & 1) ? ((lane >= 8) ? e3 : e1)
                                               : ((lane >= 8) ? e2 : e0);
            unsigned long long c1 = (lane & 1) ? ((lane >= 8) ? f3 : f1)
                                               : ((lane >= 8) ? f2 : f0);
            atomicAdd(&sc0[lane], (int)((c0 >> (slot * 16)) & 0xFFFFu));
            atomicAdd(&sc1[lane], (int)((c1 >> (slot * 16)) & 0xFFFFu));
        }
    }
    __syncthreads();
    if (tid < 16) { g_c0[tid] = sc0[tid]; g_c1[tid] = sc1[tid]; }
    if (tid == 0) g_count = 0;    // reset for next graph replay
}

// ---------------------------------------------------------------------------
// Kernel 2: pure parallel output fill (spikes [BT,10], d0 [2048,16], d1 [10,16])
// ---------------------------------------------------------------------------
__global__ void __launch_bounds__(256) k_out(float*       __restrict__ out,
                                             const float* __restrict__ map0,
                                             const float* __restrict__ map1) {
    int e = blockIdx.x * 256 + threadIdx.x;
    if (e >= TOT_OUT) return;
    float r;
    if (e < NS_OUT) {
        int bt = e / NOUT;
        int k  = e - bt * NOUT;
        unsigned s = (g_S1[bt >> 2] >> ((bt & 3) * 8)) & 0xFFu;
        unsigned msk = g_spk[s & 15];
        r = (s != 0xFFu && ((msk >> k) & 1u)) ? 1.0f : 0.0f;
    } else if (e < NS_OUT + NHID * 16) {
        int f = e - NS_OUT;
        int p = f & 15;
        r = ALPHA_F * (float)g_c0[p] * ((float)p - __ldg(&map0[f]));
    } else {
        int f = e - NS_OUT - NHID * 16;
        int p = f & 15;
        r = ALPHA_F * (float)g_c1[p] * ((float)p - __ldg(&map1[f]));
    }
    out[e] = r;
}

// ---------------------------------------------------------------------------
// Inputs (metadata order): frames, input_neuron_id, tau0, v_th0, neuron_id0,
// mem_map0, syn_w0, tau1, v_th1, neuron_id1, mem_map1, syn_w1
// ---------------------------------------------------------------------------
extern "C" void kernel_launch(void* const* d_in, const int* in_sizes, int n_in,
                              void* d_out, int out_size) {
    const int*   frames = (const int*)  d_in[0];
    const int*   inid   = (const int*)  d_in[1];
    const float* vth0   = (const float*)d_in[3];
    const int*   nid0   = (const int*)  d_in[4];
    const float* map0   = (const float*)d_in[5];
    const float* vth1   = (const float*)d_in[8];
    const float* map1   = (const float*)d_in[10];

    k_main<<<NBLK, 256>>>(frames, inid, nid0, vth0, map0, map1, vth1);
    k_out<<<(TOT_OUT + 255) / 256, 256>>>((float*)d_out, map0, map1);
}

// round 7
// speedup vs baseline: 1.5361x; 1.5361x over previous
#include <cuda_runtime.h>

// Problem constants (fixed shapes for SNNModel_67611375174158)
#define B_DIM   128
#define T_DIM   128
#define BT      (B_DIM * T_DIM)          // 16384 rows
#define NIN     2312                     // 2*34*34
#define NCH     (NIN / 4)                // 578 int4 chunks per row
#define NFULL   (NCH / 32)               // 18 full 32-chunk groups
#define NTAIL   (NCH - NFULL * 32)       // 2 tail chunks
#define NHID    2048
#define NOUT    10
#define ALPHA_F 0.001f

#define NS_OUT  (BT * NOUT)                       // 163840 spike floats
#define TOT_OUT (NS_OUT + NHID * 16 + NOUT * 16)  // 196768 total floats

#define NROWBLK (BT / 8)                          // 2048 row blocks (8 warps each)
#define NSCANBLK 16

// Scratch (no allocations -> __device__ globals)
__device__ unsigned char      g_accB[BT];         // [b*128+t]: acc & 15
__device__ unsigned           g_hasM[4];          // 128-bit has[t] mask (idempotent OR)
__device__ unsigned long long g_A1pack;           // 16 x 4-bit A1 table
__device__ unsigned           g_spk[16];          // spike bitmask per s (10 k-bits)
__device__ unsigned           g_S1[BT / 4];       // packed s1 bytes [b*32 + t/4]
__device__ int                g_cpart[NSCANBLK][32]; // per-block hist partials (c0|c1)

// ---------------------------------------------------------------------------
// Kernel 1: frame scan. One warp per (b,t) row (2312 int32). Extra block
// builds A1 pack + spike LUT concurrently. has[t] accumulated via one
// block-aggregated atomicOr (idempotent across graph replays).
// ---------------------------------------------------------------------------
__global__ void __launch_bounds__(256) k_rowacc(const int*   __restrict__ frames,
                                                const int*   __restrict__ ids,
                                                const int*   __restrict__ nid0,
                                                const float* __restrict__ vth0,
                                                const float* __restrict__ map0,
                                                const float* __restrict__ map1,
                                                const float* __restrict__ vth1) {
    int tid  = threadIdx.x;
    int lane = tid & 31;

    if (blockIdx.x == NROWBLK) {
        // ---- Table block ----
        __shared__ int sA1[16];
        if (tid < 16) sA1[tid] = 0;
        __syncthreads();
        int loc[16];
        #pragma unroll
        for (int p = 0; p < 16; p++) loc[p] = 0;
        for (int j = tid; j < NHID; j += 256) {
            int   nid = __ldg(&nid0[j]);
            float vt  = __ldg(&vth0[j]);
            const float4* r = reinterpret_cast<const float4*>(map0 + (size_t)j * 16);
            #pragma unroll
            for (int q = 0; q < 4; q++) {
                float4 mv = __ldg(&r[q]);
                if (mv.x >= vt) loc[q * 4 + 0] ^= nid;
                if (mv.y >= vt) loc[q * 4 + 1] ^= nid;
                if (mv.z >= vt) loc[q * 4 + 2] ^= nid;
                if (mv.w >= vt) loc[q * 4 + 3] ^= nid;
            }
        }
        #pragma unroll
        for (int p = 0; p < 16; p++)
            if (loc[p]) atomicXor(&sA1[p], loc[p]);
        __syncthreads();
        if (tid == 0) {
            unsigned long long pk = 0;
            #pragma unroll
            for (int p = 0; p < 16; p++)
                pk |= (unsigned long long)(sA1[p] & 15) << (4 * p);
            g_A1pack = pk;
        }
        if (tid < 16) {   // spike LUT: plain deterministic stores
            unsigned m = 0;
            #pragma unroll
            for (int k = 0; k < NOUT; k++)
                if (__ldg(&map1[k * 16 + tid]) >= __ldg(&vth1[k])) m |= 1u << k;
            g_spk[tid] = m;
        }
        return;
    }

    // ---- Row blocks ----
    __shared__ unsigned sOr;
    if (tid == 0) sOr = 0;
    __syncthreads();

    int wid = (blockIdx.x * 256 + tid) >> 5;   // row = b*128 + t
    int t   = wid & 127;

    const int4* row4 = reinterpret_cast<const int4*>(frames + (size_t)wid * NIN);
    const int4* ids4 = reinterpret_cast<const int4*>(ids);

    unsigned x = 0, any = 0;
    #pragma unroll 6
    for (int g = 0; g < NFULL; g++) {
        int4 v  = __ldg(&row4[g * 32 + lane]);
        int4 id = __ldg(&ids4[g * 32 + lane]);
        if (v.x) x ^= (unsigned)id.x & 15u;
        if (v.y) x ^= (unsigned)id.y & 15u;
        if (v.z) x ^= (unsigned)id.z & 15u;
        if (v.w) x ^= (unsigned)id.w & 15u;
        any |= (unsigned)(v.x | v.y | v.z | v.w);
    }
    if (lane < NTAIL) {
        int4 v  = __ldg(&row4[NFULL * 32 + lane]);
        int4 id = __ldg(&ids4[NFULL * 32 + lane]);
        if (v.x) x ^= (unsigned)id.x & 15u;
        if (v.y) x ^= (unsigned)id.y & 15u;
        if (v.z) x ^= (unsigned)id.z & 15u;
        if (v.w) x ^= (unsigned)id.w & 15u;
        any |= (unsigned)(v.x | v.y | v.z | v.w);
    }

    unsigned acc  = __reduce_xor_sync(0xFFFFFFFFu, x);
    unsigned anyv = __reduce_or_sync(0xFFFFFFFFu, any);

    if (lane == 0) {
        g_accB[(wid >> 7) * 128 + t] = (unsigned char)(acc & 15u);
        if (anyv) atomicOr(&sOr, 1u << (t & 31));
    }
    __syncthreads();
    if (tid == 0 && sOr) atomicOr(&g_hasM[t >> 5], sOr);  // idempotent
}

// ---------------------------------------------------------------------------
// Kernel 2: warp-per-batch prefix-XOR scan. 16 blocks x 8 warps = 128 warps.
// Lane owns 4 timesteps. Two shfl prefix scans (s0, then s1 from y=dt^A1[s0]).
// Histograms: nibble-packed per lane -> byte expand -> butterfly add ->
// per-block partials in g_cpart (summed by k_out; no reset needed).
// ---------------------------------------------------------------------------
__global__ void __launch_bounds__(256) k_scan(void) {
    __shared__ unsigned char sDt8[T_DIM];
    __shared__ unsigned char sAm8[T_DIM];
    __shared__ int           sc[32];

    int tid  = threadIdx.x;
    int lane = tid & 31;
    int wrp  = tid >> 5;

    if (tid < 32) sc[tid] = 0;

    // Phase C: per-t dt/am from the 128-bit mask (threads 0-127)
    if (tid < 128) {
        unsigned m0 = __ldg(&g_hasM[0]), m1 = __ldg(&g_hasM[1]);
        unsigned m2 = __ldg(&g_hasM[2]), m3 = __ldg(&g_hasM[3]);
        int t = tid, w = t >> 5, bit = t & 31;
        unsigned mw  = (w == 0) ? m0 : (w == 1) ? m1 : (w == 2) ? m2 : m3;
        int active = (mw >> bit) & 1;
        unsigned low = mw & ((bit ? (1u << bit) : 1u) - 1u);  // bits strictly below t
        if (bit == 0) low = 0;
        unsigned q0 = (w == 0) ? low : m0;
        unsigned q1 = (w == 1) ? low : ((w > 1) ? m1 : 0u);
        unsigned q2 = (w == 2) ? low : ((w > 2) ? m2 : 0u);
        unsigned q3 = (w == 3) ? low : 0u;
        int tl = q3 ? (96 + 31 - __clz(q3))
               : q2 ? (64 + 31 - __clz(q2))
               : q1 ? (32 + 31 - __clz(q1))
               : q0 ? (31 - __clz(q0)) : 0;
        sDt8[t] = (unsigned char)(active ? ((t - tl) & 15) : 0);
        sAm8[t] = (unsigned char)(active ? 0x0F : 0x00);
    }
    __syncthreads();

    int b = blockIdx.x * 8 + wrp;                    // batch for this warp
    unsigned accW = __ldg(&reinterpret_cast<const unsigned*>(g_accB)[b * 32 + lane]);
    unsigned dtW  = reinterpret_cast<const unsigned*>(sDt8)[lane];
    unsigned amW  = reinterpret_cast<const unsigned*>(sAm8)[lane];
    unsigned long long A1p = g_A1pack;

    // s0 pass: x = (acc & am) ^ dt, segment xor, exclusive warp prefix
    unsigned xw = (accW & amW) ^ dtW;
    unsigned fold = xw ^ (xw >> 16);  fold ^= fold >> 8;
    unsigned Xl = fold & 15u;
    unsigned pref = Xl;
    #pragma unroll
    for (int o = 1; o < 32; o <<= 1) {
        unsigned v = __shfl_up_sync(0xFFFFFFFFu, pref, o);
        if (lane >= o) pref ^= v;
    }
    unsigned c = pref ^ Xl;                          // exclusive carry

    unsigned long long h0 = 0, h1 = 0;               // nibble-packed histograms
    unsigned yw = 0;
    #pragma unroll
    for (int j = 0; j < 4; j++) {
        unsigned act = (amW >> (8 * j)) & 1u;
        unsigned xb  = (xw >> (8 * j)) & 15u;
        c ^= xb;                                     // s0 inclusive
        h0 += (unsigned long long)act << (c * 4);
        unsigned a1 = act ? ((unsigned)(A1p >> (c * 4)) & 15u) : 0u;
        unsigned db = (dtW >> (8 * j)) & 15u;
        yw |= (db ^ a1) << (8 * j);
    }

    // s1 pass: prefix over y
    fold = yw ^ (yw >> 16);  fold ^= fold >> 8;
    unsigned Yl = fold & 15u;
    pref = Yl;
    #pragma unroll
    for (int o = 1; o < 32; o <<= 1) {
        unsigned v = __shfl_up_sync(0xFFFFFFFFu, pref, o);
        if (lane >= o) pref ^= v;
    }
    unsigned d = pref ^ Yl;

    unsigned outw = 0;
    #pragma unroll
    for (int j = 0; j < 4; j++) {
        unsigned act = (amW >> (8 * j)) & 1u;
        unsigned yb  = (yw >> (8 * j)) & 15u;
        d ^= yb;                                     // s1 inclusive
        h1 += (unsigned long long)act << (d * 4);
        unsigned sb = act ? d : 0xFFu;
        outw |= sb << (8 * j);
    }
    g_S1[b * 32 + lane] = outw;

    // Histogram reduce: nibble->byte expand (bins<=4/lane, <=128/warp) + butterfly
    auto spread = [](unsigned v) -> unsigned long long {
        unsigned long long s = v;
        s = (s | (s << 16)) & 0x0000FFFF0000FFFFULL;
        s = (s | (s << 8))  & 0x00FF00FF00FF00FFULL;
        s = (s | (s << 4))  & 0x0F0F0F0F0F0F0F0FULL;
        return s;
    };
    unsigned long long e0 = spread((unsigned)h0);          // c0 bins 0-7
    unsigned long long e1 = spread((unsigned)(h0 >> 32));  // c0 bins 8-15
    unsigned long long f0 = spread((unsigned)h1);          // c1 bins 0-7
    unsigned long long f1 = spread((unsigned)(h1 >> 32));  // c1 bins 8-15
    #pragma unroll
    for (int o = 16; o; o >>= 1) {
        e0 += __shfl_xor_sync(0xFFFFFFFFu, e0, o);
        e1 += __shfl_xor_sync(0xFFFFFFFFu, e1, o);
        f0 += __shfl_xor_sync(0xFFFFFFFFu, f0, o);
        f1 += __shfl_xor_sync(0xFFFFFFFFu, f1, o);
    }
    if (lane < 16) {
        unsigned long long c0v = (lane < 8) ? e0 : e1;
        unsigned long long c1v = (lane < 8) ? f0 : f1;
        int sh = (lane & 7) * 8;
        atomicAdd(&sc[lane],      (int)((c0v >> sh) & 255u));
        atomicAdd(&sc[16 + lane], (int)((c1v >> sh) & 255u));
    }
    __syncthreads();
    if (tid < 32) g_cpart[blockIdx.x][tid] = sc[tid];   // plain store, replay-safe
}

// ---------------------------------------------------------------------------
// Kernel 3: output fill (spikes [BT,10], d0 [2048,16], d1 [10,16]).
// First folds the 16 histogram partials in smem.
// ---------------------------------------------------------------------------
__global__ void __launch_bounds__(256) k_out(float*       __restrict__ out,
                                             const float* __restrict__ map0,
                                             const float* __restrict__ map1) {
    __shared__ int sc[32];
    int tid = threadIdx.x;
    if (tid < 32) {
        int v = 0;
        #pragma unroll
        for (int k = 0; k < NSCANBLK; k++) v += __ldg(&g_cpart[k][tid]);
        sc[tid] = v;
    }
    __syncthreads();

    int e = blockIdx.x * 256 + tid;
    if (e >= TOT_OUT) return;
    float r;
    if (e < NS_OUT) {
        int bt = e / NOUT;
        int k  = e - bt * NOUT;
        unsigned s = (__ldg(&g_S1[bt >> 2]) >> ((bt & 3) * 8)) & 0xFFu;
        unsigned msk = g_spk[s & 15];
        r = (s != 0xFFu && ((msk >> k) & 1u)) ? 1.0f : 0.0f;
    } else if (e < NS_OUT + NHID * 16) {
        int f = e - NS_OUT;
        int p = f & 15;
        r = ALPHA_F * (float)sc[p] * ((float)p - __ldg(&map0[f]));
    } else {
        int f = e - NS_OUT - NHID * 16;
        int p = f & 15;
        r = ALPHA_F * (float)sc[16 + p] * ((float)p - __ldg(&map1[f]));
    }
    out[e] = r;
}

// ---------------------------------------------------------------------------
// Inputs (metadata order): frames, input_neuron_id, tau0, v_th0, neuron_id0,
// mem_map0, syn_w0, tau1, v_th1, neuron_id1, mem_map1, syn_w1
// ---------------------------------------------------------------------------
extern "C" void kernel_launch(void* const* d_in, const int* in_sizes, int n_in,
                              void* d_out, int out_size) {
    const int*   frames = (const int*)  d_in[0];
    const int*   inid   = (const int*)  d_in[1];
    const float* vth0   = (const float*)d_in[3];
    const int*   nid0   = (const int*)  d_in[4];
    const float* map0   = (const float*)d_in[5];
    const float* vth1   = (const float*)d_in[8];
    const float* map1   = (const float*)d_in[10];

    k_rowacc<<<NROWBLK + 1, 256>>>(frames, inid, nid0, vth0, map0, map1, vth1);
    k_scan<<<NSCANBLK, 256>>>();
    k_out<<<(TOT_OUT + 255) / 256, 256>>>((float*)d_out, map0, map1);
}